// round 10
// baseline (speedup 1.0000x reference)
#include <cuda_runtime.h>

#define DIM 16384
#define OUTN 1000
#define TPB 256

typedef unsigned long long ull;

// 26 fused two-qubit gate matrices (4x4 each): e_k=k, o_k=7+k, f_k=14+k, p_k=21+k
__device__ float d_G[448];

// ---------------------------------------------------------------------------
// Prep: build fused gates (verified correct R3-R7).
// ---------------------------------------------------------------------------
__global__ void qnn_prep(const float* __restrict__ w, const float* __restrict__ bias) {
    int g = threadIdx.x;
    if (g >= 26) return;
    int stage, p;
    if (g < 7)       { stage = 0; p = g; }
    else if (g < 13) { stage = 1; p = g - 7; }
    else if (g < 20) { stage = 2; p = g - 13; }
    else             { stage = 3; p = g - 20; }
    int l = stage >> 1;
    int par = stage & 1;
    int i = par ? (11 - 2 * p) : (12 - 2 * p);

    float thH = 0.5f * w[l * 26 + i * 2 + 0];
    float thL = 0.5f * w[l * 26 + i * 2 + 1];
    float A[4] = { cosf(thH), -sinf(thH), sinf(thH), cosf(thH) };
    float B[4] = { cosf(thL), -sinf(thL), sinf(thL), cosf(thL) };
    float G[16];
    for (int mp = 0; mp < 4; mp++)
        for (int m = 0; m < 4; m++) {
            float v = A[(mp >> 1) * 2 + (m >> 1)] * B[(mp & 1) * 2 + (m & 1)];
            G[mp * 4 + m] = (m == 3) ? -v : v;   // CZ applied first
        }
    if (stage == 0) {
        float bH = 0.5f * bias[i], bL = 0.5f * bias[i + 1];
        float Ab[4] = { cosf(bH), -sinf(bH), sinf(bH), cosf(bH) };
        float Bb[4] = { cosf(bL), -sinf(bL), sinf(bL), cosf(bL) };
        float Gb[16];
        for (int mp = 0; mp < 4; mp++)
            for (int m = 0; m < 4; m++)
                Gb[mp * 4 + m] = Ab[(mp >> 1) * 2 + (m >> 1)] * Bb[(mp & 1) * 2 + (m & 1)];
        float GG[16];
        for (int a = 0; a < 4; a++)
            for (int c = 0; c < 4; c++) {
                float s = 0.f;
                for (int k = 0; k < 4; k++) s += G[a * 4 + k] * Gb[k * 4 + c];
                GG[a * 4 + c] = s;               // apply bias first
            }
        for (int x = 0; x < 16; x++) G[x] = GG[x];
    }
    for (int x = 0; x < 26; x++) {}  // no-op
    for (int x = 0; x < 16; x++) d_G[(stage * 7 + p) * 16 + x] = G[x];
}

// ---------------------------------------------------------------------------
// GF(2)-linear bank swizzle for the R8 thread maps:
//   bank ^= P3*011 ^ P4*100 ^ P5*010 ^ P6*001 ^ P7*010 ^ P8*010 ^ P9*100
// Per pass, the 3 lane-phase address bits map to independent bank vectors:
//   P1 {P4,P5,P6}->{100,010,001}; P2/P7 {P0,P1,P2}; P3 {P0,P2,P3}->{001,100,011};
//   P4 {P0,P8,P9}->{001,010,100}; P5 {P1,P2,P3}->{010,100,011};
//   P6 {P3,P4,P7}->{011,100,010}. All verified independent.
// ---------------------------------------------------------------------------
__host__ __device__ __forceinline__ constexpr int swzF(int P) {
    return P ^ ( ((P >> 3 ^ P >> 6) & 1)
              | (((P >> 3 ^ P >> 5 ^ P >> 7 ^ P >> 8) & 1) << 1)
              | (((P >> 4 ^ P >> 9) & 1) << 2) );
}

// ---------------------------------------------------------------------------
// Packed f32x2 helpers (FFMA2 — ptxas never emits from C++)
// ---------------------------------------------------------------------------
__device__ __forceinline__ ull f2mul(ull a, ull b) {
    ull d; asm("mul.rn.f32x2 %0, %1, %2;" : "=l"(d) : "l"(a), "l"(b)); return d;
}
__device__ __forceinline__ ull f2fma(ull a, ull b, ull c) {
    ull d; asm("fma.rn.f32x2 %0, %1, %2, %3;" : "=l"(d) : "l"(a), "l"(b), "l"(c)); return d;
}
__device__ __forceinline__ void up2(ull a, float& x, float& y) {
    asm("mov.b64 {%0, %1}, %2;" : "=f"(x), "=f"(y) : "l"(a));
}
__device__ __forceinline__ ull pk2(float x, float y) {
    ull a; asm("mov.b64 %0, {%1, %2};" : "=l"(a) : "f"(x), "f"(y)); return a;
}

struct G16  { float g[16]; };
struct G16P { ull   g[16]; };

__device__ __forceinline__ G16 ldGm(const float* sG, int i) {
    G16 r;
    #pragma unroll
    for (int x = 0; x < 16; x++) r.g[x] = sG[i * 16 + x];
    return r;
}
__device__ __forceinline__ G16P ldGp(const ull* sGp, int i) {
    G16P r;
    #pragma unroll
    for (int x = 0; x < 16; x++) r.g[x] = sGp[i * 16 + x];
    return r;
}

__device__ __forceinline__ void gate4(const G16& G, float& a, float& b, float& c, float& d) {
    float x = a, y = b, z = c, w = d;
    a = G.g[0]  * x + G.g[1]  * y + G.g[2]  * z + G.g[3]  * w;
    b = G.g[4]  * x + G.g[5]  * y + G.g[6]  * z + G.g[7]  * w;
    c = G.g[8]  * x + G.g[9]  * y + G.g[10] * z + G.g[11] * w;
    d = G.g[12] * x + G.g[13] * y + G.g[14] * z + G.g[15] * w;
}
__device__ __forceinline__ void gate4p(const G16P& G, ull& a, ull& b, ull& c, ull& d) {
    ull x = a, y = b, z = c, w = d;
    a = f2fma(G.g[3],  w, f2fma(G.g[2],  z, f2fma(G.g[1],  y, f2mul(G.g[0],  x))));
    b = f2fma(G.g[7],  w, f2fma(G.g[6],  z, f2fma(G.g[5],  y, f2mul(G.g[4],  x))));
    c = f2fma(G.g[11], w, f2fma(G.g[10], z, f2fma(G.g[9],  y, f2mul(G.g[8],  x))));
    d = f2fma(G.g[15], w, f2fma(G.g[14], z, f2fma(G.g[13], y, f2mul(G.g[12], x))));
}

// gate on amp bits (1,0): mixes inside the float4 -> scalar path
__device__ __forceinline__ void op_vecS(const G16& G, ulonglong2 v[16]) {
    #pragma unroll
    for (int q = 0; q < 16; q++) {
        float a, b, c, d;
        up2(v[q].x, a, b); up2(v[q].y, c, d);
        gate4(G, a, b, c, d);
        v[q].x = pk2(a, b); v[q].y = pk2(c, d);
    }
}
// gate on q bits (1,0)
__device__ __forceinline__ void op_qlowP(const G16P& G, ulonglong2 v[16]) {
    #pragma unroll
    for (int h = 0; h < 16; h += 4) {
        gate4p(G, v[h].x, v[h+1].x, v[h+2].x, v[h+3].x);
        gate4p(G, v[h].y, v[h+1].y, v[h+2].y, v[h+3].y);
    }
}
// gate on q bits (3,2)
__device__ __forceinline__ void op_qhighP(const G16P& G, ulonglong2 v[16]) {
    #pragma unroll
    for (int j = 0; j < 4; j++) {
        gate4p(G, v[j].x, v[j+4].x, v[j+8].x, v[j+12].x);
        gate4p(G, v[j].y, v[j+4].y, v[j+8].y, v[j+12].y);
    }
}
// gate on q bits (2,1)
__device__ __forceinline__ void op_g43P(const G16P& G, ulonglong2 v[16]) {
    #pragma unroll
    for (int j3 = 0; j3 < 2; j3++)
        #pragma unroll
        for (int j0 = 0; j0 < 2; j0++) {
            int b0 = j0 + 8 * j3;
            gate4p(G, v[b0].x, v[b0+2].x, v[b0+4].x, v[b0+6].x);
            gate4p(G, v[b0].y, v[b0+2].y, v[b0+4].y, v[b0+6].y);
        }
}
// gate hi = q bit0, lo = amp bit1 (.x/.y halves)
__device__ __forceinline__ void op_g21P(const G16P& G, ulonglong2 v[16]) {
    #pragma unroll
    for (int h = 0; h < 16; h += 2)
        gate4p(G, v[h].x, v[h].y, v[h+1].x, v[h+1].y);
}

// q placed at f4-index bits [S, S+3]; per-q offset is a compile-time XOR
template<int S>
__device__ __forceinline__ void ldvS(const ulonglong2* s4, int base, ulonglong2 v[16]) {
    #pragma unroll
    for (int q = 0; q < 16; q++) v[q] = s4[base ^ swzF(q << S)];
}
template<int S>
__device__ __forceinline__ void stvS(ulonglong2* s4, int base, const ulonglong2 v[16]) {
    #pragma unroll
    for (int q = 0; q < 16; q++) s4[base ^ swzF(q << S)] = v[q];
}
// P3 store: only q>=8 (f4 bit11 = q bit3 set)
__device__ __forceinline__ void stv8hi(ulonglong2* s4, int base, const ulonglong2 v[16]) {
    #pragma unroll
    for (int q = 8; q < 16; q++) s4[base ^ swzF(q << 8)] = v[q];
}
// P6 irregular window {1,2,5,6}: q bits 0,1 -> f4 bits 1,2; q bits 2,3 -> f4 bits 5,6
__device__ __forceinline__ void ldv6(const ulonglong2* s4, int base, ulonglong2 v[16]) {
    #pragma unroll
    for (int q = 0; q < 16; q++)
        v[q] = s4[base ^ swzF(((q & 3) << 1) | ((q >> 2) << 5))];
}
__device__ __forceinline__ void stv6(ulonglong2* s4, int base, const ulonglong2 v[16]) {
    #pragma unroll
    for (int q = 0; q < 16; q++)
        s4[base ^ swzF(((q & 3) << 1) | ((q >> 2) << 5))] = v[q];
}

// ---------------------------------------------------------------------------
// Main kernel: 1 CTA/row, 7 fused passes, warp-local sync on P1->P2, P3->P4,
// P5->P6 (thread maps chosen so producers == consumer's warp); full barriers
// only at P2->P3, P4->P5, P6->P7. Dead cone (amp bit13=1) from P4 on.
// ---------------------------------------------------------------------------
__global__ void __launch_bounds__(TPB, 2) qnn_main(const float* __restrict__ in,
                                                   float* __restrict__ out) {
    extern __shared__ float sm[];
    ulonglong2* s4 = (ulonglong2*)sm;            // 16384 floats state
    ull*   sGp  = (ull*)(sm + DIM);              // 448 splatted gate coeffs
    float* sGs  = sm + DIM + 896;                // 448 scalar gate coeffs
    float* red  = sGs + 448;
    float* pinv = red + 8;
    const int t = threadIdx.x;
    const int b = blockIdx.x;

    for (int x = t; x < 448; x += TPB) {
        float g = d_G[x];
        sGs[x] = g;
        sGp[x] = pk2(g, g);
    }

    // ---- P1: global load in tile order + sum-of-squares
    const ulonglong2* g4 = (const ulonglong2*)(in + (size_t)b * DIM);
    ulonglong2 v[16];
    ull ssp = 0ull;
    #pragma unroll
    for (int q = 0; q < 16; q++) {
        v[q] = g4[(t << 4) | q];
        ssp = f2fma(v[q].x, v[q].x, ssp);
        ssp = f2fma(v[q].y, v[q].y, ssp);
    }
    float s0, s1; up2(ssp, s0, s1);
    float ss = s0 + s1;
    #pragma unroll
    for (int o = 16; o; o >>= 1) ss += __shfl_xor_sync(0xffffffffu, ss, o);
    if ((t & 31) == 0) red[t >> 5] = ss;
    __syncthreads();                      // B1: gate tables + red
    if (t == 0) {
        float tot = 0.f;
        #pragma unroll
        for (int k = 0; k < 8; k++) tot += red[k];
        pinv[0] = 1.0f / tot;             // read in P7, ordered by B2..B4
    }

    // P1 gates, σ1: f4 bits 4..11 = t (warp bits -> P9,P10,P11)
    { G16  g = ldGm(sGs, 0);  op_vecS(g, v); }         // e0 (1,0)
    { G16P g = ldGp(sGp, 1);  op_qlowP(g, v); }        // e1 (3,2)
    { G16P g = ldGp(sGp, 2);  op_qhighP(g, v); }       // e2 (5,4)
    { G16P g = ldGp(sGp, 7);  op_g21P(g, v); }         // o0 (2,1)
    { G16P g = ldGp(sGp, 8);  op_g43P(g, v); }         // o1 (4,3)
    { G16  g = ldGm(sGs, 14); op_vecS(g, v); }         // f0 (1,0)
    { G16P g = ldGp(sGp, 15); op_qlowP(g, v); }        // f1 (3,2)
    { G16P g = ldGp(sGp, 21); op_g21P(g, v); }         // p0 (2,1)
    { int base = swzF(t << 4); stvS<0>(s4, base, v); }
    __syncwarp();                         // P1->P2 warp-local

    // ---- P2, window f4{4..7}: e3,e4,o3  (σ2: P0..P3=t0..3, P8..P11=t4..7)
    { int base = swzF((t & 15) | ((t >> 4) << 8));
      ldvS<4>(s4, base, v);
      { G16P g = ldGp(sGp, 3);  op_qlowP(g, v); }      // e3 (7,6)
      { G16P g = ldGp(sGp, 4);  op_qhighP(g, v); }     // e4 (9,8)
      { G16P g = ldGp(sGp, 10); op_g43P(g, v); }       // o3 (8,7)
      stvS<4>(s4, base, v); }
    __syncthreads();                      // B2: P2->P3 (cross-warp)

    // ---- P3, window f4{8..11}: e5,e6,o5,f6; store bit13=1 half only
    // σ3: P0=t0, P1=t5, P2..P5=t1..t4, P6=t6, P7=t7 (warp bits -> P1,P6,P7)
    { int base = swzF((t & 1) | (((t >> 5) & 1) << 1)
                      | (((t >> 1) & 15) << 2) | (((t >> 6) & 3) << 6));
      ldvS<8>(s4, base, v);
      { G16P g = ldGp(sGp, 5);  op_qlowP(g, v); }      // e5 (11,10)
      { G16P g = ldGp(sGp, 6);  op_qhighP(g, v); }     // e6 (13,12)
      { G16P g = ldGp(sGp, 12); op_g43P(g, v); }       // o5 (12,11)
      { G16P g = ldGp(sGp, 20); op_qhighP(g, v); }     // f6 (13,12)
      stv8hi(s4, base, v); }
    __syncwarp();                         // P3->P4 warp-local

    // ---- P4, window f4{2..5}: o2,f2,f3,p2 — active lanes t4==0 (16/warp)
    // σ4: P0=t0, P1=t5, P6=t6, P7=t7, P8..P10=t1..t3, P11=1
    if (!(t & 16)) {
      int base = swzF((t & 1) | (((t >> 5) & 1) << 1) | (((t >> 6) & 3) << 6)
                      | (((t >> 1) & 7) << 8) | 2048);
      ldvS<2>(s4, base, v);
      { G16P g = ldGp(sGp, 9);  op_g43P(g, v); }       // o2 (6,5)
      { G16P g = ldGp(sGp, 16); op_qlowP(g, v); }      // f2 (5,4)
      { G16P g = ldGp(sGp, 17); op_qhighP(g, v); }     // f3 (7,6)
      { G16P g = ldGp(sGp, 23); op_g43P(g, v); }       // p2 (6,5)
      stvS<2>(s4, base, v);
    }
    __syncthreads();                      // B3: P4->P5 (cross-warp)

    // ---- P5, window f4{6..9}: o4,f4,f5,p4 — warps 4..7 (t>=128)
    // σ5: P0=t5, P1..P5=t0..t4, P10=t6, P11=1 (warp bits -> P0,P10,P11)
    if (t >= 128) {
      int base = swzF(((t >> 5) & 1) | ((t & 31) << 1)
                      | (((t >> 6) & 1) << 10) | 2048);
      ldvS<6>(s4, base, v);
      { G16P g = ldGp(sGp, 11); op_g43P(g, v); }       // o4 (10,9)
      { G16P g = ldGp(sGp, 18); op_qlowP(g, v); }      // f4 (9,8)
      { G16P g = ldGp(sGp, 19); op_qhighP(g, v); }     // f5 (11,10)
      { G16P g = ldGp(sGp, 25); op_g43P(g, v); }       // p4 (10,9)
      stvS<6>(s4, base, v);
    }
    __syncwarp();                         // P5->P6 warp-local

    // ---- P6, window f4{1,2,5,6}: p1,p3 — warps 4..7 (t>=128)
    // σ6: P0=t5, P3=t0, P4=t1, P7=t2, P8=t3, P9=t4, P10=t6, P11=1
    if (t >= 128) {
      int base = swzF(((t >> 5) & 1) | ((t & 3) << 3) | (((t >> 2) & 1) << 7)
                      | (((t >> 3) & 3) << 8) | (((t >> 6) & 1) << 10) | 2048);
      ldv6(s4, base, v);
      { G16P g = ldGp(sGp, 22); op_qlowP(g, v); }      // p1 (4,3)
      { G16P g = ldGp(sGp, 24); op_qhighP(g, v); }     // p3 (8,7)
      stv6(s4, base, v);
    }
    __syncthreads();                      // B4: P6->P7 (cross-warp)

    // ---- P7: p5 (12,11) row m=3 only + output (amps j >= 15384, bit13=1)
    if (t >= 6) {
        ulonglong2 v0 = s4[swzF(2304 + t)];   // (P10,P9)=(0,0)
        ulonglong2 v1 = s4[swzF(2816 + t)];   // (0,1)
        ulonglong2 v2 = s4[swzF(3328 + t)];   // (1,0)
        ulonglong2 v3 = s4[swzF(3840 + t)];   // (1,1)
        G16P g = ldGp(sGp, 26);                        // p5
        ull dx = f2fma(g.g[15], v3.x, f2fma(g.g[14], v2.x,
                 f2fma(g.g[13], v1.x, f2mul(g.g[12], v0.x))));
        ull dy = f2fma(g.g[15], v3.y, f2fma(g.g[14], v2.y,
                 f2fma(g.g[13], v1.y, f2mul(g.g[12], v0.y))));
        float inv = pinv[0];
        ull invp = pk2(inv, inv);
        ulonglong2 r;
        r.x = f2mul(f2mul(dx, dx), invp);
        r.y = f2mul(f2mul(dy, dy), invp);
        *(ulonglong2*)(out + (size_t)b * OUTN + 4 * t - 24) = r;
    }
}

extern "C" void kernel_launch(void* const* d_in, const int* in_sizes, int n_in,
                              void* d_out, int out_size) {
    const float* in   = (const float*)d_in[0];
    const float* w    = (const float*)d_in[1];
    const float* bias = (const float*)d_in[2];
    float* out = (float*)d_out;
    int B = in_sizes[0] / DIM;   // 512

    const int smem_bytes = (DIM + 896 + 448 + 8 + 8) * (int)sizeof(float);  // ~71 KB
    cudaFuncSetAttribute(qnn_main, cudaFuncAttributeMaxDynamicSharedMemorySize, smem_bytes);

    qnn_prep<<<1, 32>>>(w, bias);
    qnn_main<<<B, TPB, smem_bytes>>>(in, out);
}

// round 12
// speedup vs baseline: 1.0890x; 1.0890x over previous
#include <cuda_runtime.h>

#define DIM 16384
#define OUTN 1000
#define TPB 256

typedef unsigned long long ull;

// 26 fused two-qubit gate matrices (4x4 each): e_k=k, o_k=7+k, f_k=14+k, p_k=21+k
__device__ float d_G[448];

// ---------------------------------------------------------------------------
// Prep: build fused gates (verified correct R3-R10).
// ---------------------------------------------------------------------------
__global__ void qnn_prep(const float* __restrict__ w, const float* __restrict__ bias) {
    int g = threadIdx.x;
    if (g >= 26) return;
    int stage, p;
    if (g < 7)       { stage = 0; p = g; }
    else if (g < 13) { stage = 1; p = g - 7; }
    else if (g < 20) { stage = 2; p = g - 13; }
    else             { stage = 3; p = g - 20; }
    int l = stage >> 1;
    int par = stage & 1;
    int i = par ? (11 - 2 * p) : (12 - 2 * p);

    float thH = 0.5f * w[l * 26 + i * 2 + 0];
    float thL = 0.5f * w[l * 26 + i * 2 + 1];
    float A[4] = { cosf(thH), -sinf(thH), sinf(thH), cosf(thH) };
    float B[4] = { cosf(thL), -sinf(thL), sinf(thL), cosf(thL) };
    float G[16];
    for (int mp = 0; mp < 4; mp++)
        for (int m = 0; m < 4; m++) {
            float v = A[(mp >> 1) * 2 + (m >> 1)] * B[(mp & 1) * 2 + (m & 1)];
            G[mp * 4 + m] = (m == 3) ? -v : v;   // CZ applied first
        }
    if (stage == 0) {
        float bH = 0.5f * bias[i], bL = 0.5f * bias[i + 1];
        float Ab[4] = { cosf(bH), -sinf(bH), sinf(bH), cosf(bH) };
        float Bb[4] = { cosf(bL), -sinf(bL), sinf(bL), cosf(bL) };
        float Gb[16];
        for (int mp = 0; mp < 4; mp++)
            for (int m = 0; m < 4; m++)
                Gb[mp * 4 + m] = Ab[(mp >> 1) * 2 + (m >> 1)] * Bb[(mp & 1) * 2 + (m & 1)];
        float GG[16];
        for (int a = 0; a < 4; a++)
            for (int c = 0; c < 4; c++) {
                float s = 0.f;
                for (int k = 0; k < 4; k++) s += G[a * 4 + k] * Gb[k * 4 + c];
                GG[a * 4 + c] = s;               // apply bias first
            }
        for (int x = 0; x < 16; x++) G[x] = GG[x];
    }
    for (int x = 0; x < 16; x++) d_G[(stage * 7 + p) * 16 + x] = G[x];
}

// ---------------------------------------------------------------------------
// GF(2)-linear swizzle (R6, verified): bank bit2 ^= b3^b6, bit1 ^= b4, bit0 ^= b5
// ---------------------------------------------------------------------------
__host__ __device__ __forceinline__ constexpr int swzF(int P) {
    return P ^ (((((P >> 3) ^ (P >> 6)) & 1) << 2)
             |  ((((P >> 4)) & 1) << 1)
             |  (((P >> 5)) & 1));
}

// ---------------------------------------------------------------------------
// Packed f32x2 helpers (FFMA2 — ptxas never emits from C++)
// ---------------------------------------------------------------------------
__device__ __forceinline__ ull f2mul(ull a, ull b) {
    ull d; asm("mul.rn.f32x2 %0, %1, %2;" : "=l"(d) : "l"(a), "l"(b)); return d;
}
__device__ __forceinline__ ull f2fma(ull a, ull b, ull c) {
    ull d; asm("fma.rn.f32x2 %0, %1, %2, %3;" : "=l"(d) : "l"(a), "l"(b), "l"(c)); return d;
}
__device__ __forceinline__ void up2(ull a, float& x, float& y) {
    asm("mov.b64 {%0, %1}, %2;" : "=f"(x), "=f"(y) : "l"(a));
}
__device__ __forceinline__ ull pk2(float x, float y) {
    ull a; asm("mov.b64 %0, {%1, %2};" : "=l"(a) : "f"(x), "f"(y)); return a;
}

struct G16  { float g[16]; };
struct G16P { ull   g[16]; };

// vectorized coefficient loads: 4x LDS.128 (scalar) / 8x LDS.128 (packed)
__device__ __forceinline__ G16 ldGm(const float* sG, int i) {
    G16 r;
    const float4* p = (const float4*)(sG + i * 16);
    #pragma unroll
    for (int x = 0; x < 4; x++) {
        float4 f = p[x];
        r.g[4*x] = f.x; r.g[4*x+1] = f.y; r.g[4*x+2] = f.z; r.g[4*x+3] = f.w;
    }
    return r;
}
__device__ __forceinline__ G16P ldGp(const ull* sGp, int i) {
    G16P r;
    const ulonglong2* p = (const ulonglong2*)(sGp + i * 16);
    #pragma unroll
    for (int x = 0; x < 8; x++) {
        ulonglong2 u = p[x];
        r.g[2*x] = u.x; r.g[2*x+1] = u.y;
    }
    return r;
}

__device__ __forceinline__ void gate4(const G16& G, float& a, float& b, float& c, float& d) {
    float x = a, y = b, z = c, w = d;
    a = G.g[0]  * x + G.g[1]  * y + G.g[2]  * z + G.g[3]  * w;
    b = G.g[4]  * x + G.g[5]  * y + G.g[6]  * z + G.g[7]  * w;
    c = G.g[8]  * x + G.g[9]  * y + G.g[10] * z + G.g[11] * w;
    d = G.g[12] * x + G.g[13] * y + G.g[14] * z + G.g[15] * w;
}
__device__ __forceinline__ void gate4p(const G16P& G, ull& a, ull& b, ull& c, ull& d) {
    ull x = a, y = b, z = c, w = d;
    a = f2fma(G.g[3],  w, f2fma(G.g[2],  z, f2fma(G.g[1],  y, f2mul(G.g[0],  x))));
    b = f2fma(G.g[7],  w, f2fma(G.g[6],  z, f2fma(G.g[5],  y, f2mul(G.g[4],  x))));
    c = f2fma(G.g[11], w, f2fma(G.g[10], z, f2fma(G.g[9],  y, f2mul(G.g[8],  x))));
    d = f2fma(G.g[15], w, f2fma(G.g[14], z, f2fma(G.g[13], y, f2mul(G.g[12], x))));
}
// rows 2,3 only (outputs c,d); a,b positions left stale (dead downstream)
__device__ __forceinline__ void gate4p_hi(const G16P& G, ull x, ull y, ull& z, ull& w) {
    ull zi = z, wi = w;
    z = f2fma(G.g[11], wi, f2fma(G.g[10], zi, f2fma(G.g[9],  y, f2mul(G.g[8],  x))));
    w = f2fma(G.g[15], wi, f2fma(G.g[14], zi, f2fma(G.g[13], y, f2mul(G.g[12], x))));
}

// gate on amp bits (1,0): mixes inside the float4 -> scalar path
__device__ __forceinline__ void op_vecS(const G16& G, ulonglong2 v[16]) {
    #pragma unroll
    for (int q = 0; q < 16; q++) {
        float a, b, c, d;
        up2(v[q].x, a, b); up2(v[q].y, c, d);
        gate4(G, a, b, c, d);
        v[q].x = pk2(a, b); v[q].y = pk2(c, d);
    }
}
// gate on q bits (1,0)
__device__ __forceinline__ void op_qlowP(const G16P& G, ulonglong2 v[16]) {
    #pragma unroll
    for (int h = 0; h < 16; h += 4) {
        gate4p(G, v[h].x, v[h+1].x, v[h+2].x, v[h+3].x);
        gate4p(G, v[h].y, v[h+1].y, v[h+2].y, v[h+3].y);
    }
}
// gate on q bits (3,2)
__device__ __forceinline__ void op_qhighP(const G16P& G, ulonglong2 v[16]) {
    #pragma unroll
    for (int j = 0; j < 4; j++) {
        gate4p(G, v[j].x, v[j+4].x, v[j+8].x, v[j+12].x);
        gate4p(G, v[j].y, v[j+4].y, v[j+8].y, v[j+12].y);
    }
}
// gate on q bits (2,1)
__device__ __forceinline__ void op_g43P(const G16P& G, ulonglong2 v[16]) {
    #pragma unroll
    for (int j3 = 0; j3 < 2; j3++)
        #pragma unroll
        for (int j0 = 0; j0 < 2; j0++) {
            int b0 = j0 + 8 * j3;
            gate4p(G, v[b0].x, v[b0+2].x, v[b0+4].x, v[b0+6].x);
            gate4p(G, v[b0].y, v[b0+2].y, v[b0+4].y, v[b0+6].y);
        }
}
// gate on q bits (2,1), output rows m=2,3 only (m=0,1 dead downstream)
__device__ __forceinline__ void op_g43P_hi(const G16P& G, ulonglong2 v[16]) {
    #pragma unroll
    for (int j3 = 0; j3 < 2; j3++)
        #pragma unroll
        for (int j0 = 0; j0 < 2; j0++) {
            int b0 = j0 + 8 * j3;
            gate4p_hi(G, v[b0].x, v[b0+2].x, v[b0+4].x, v[b0+6].x);
            gate4p_hi(G, v[b0].y, v[b0+2].y, v[b0+4].y, v[b0+6].y);
        }
}
// gate hi = q bit0, lo = amp bit1 (.x/.y halves)
__device__ __forceinline__ void op_g21P(const G16P& G, ulonglong2 v[16]) {
    #pragma unroll
    for (int h = 0; h < 16; h += 2)
        gate4p(G, v[h].x, v[h].y, v[h+1].x, v[h+1].y);
}

// q placed at f4-index bits [S, S+3]; per-q offset is a compile-time XOR
template<int S>
__device__ __forceinline__ void ldvS(const ulonglong2* s4, int base, ulonglong2 v[16]) {
    #pragma unroll
    for (int q = 0; q < 16; q++) v[q] = s4[base ^ swzF(q << S)];
}
template<int S>
__device__ __forceinline__ void stvS(ulonglong2* s4, int base, const ulonglong2 v[16]) {
    #pragma unroll
    for (int q = 0; q < 16; q++) s4[base ^ swzF(q << S)] = v[q];
}
// P3 store: only q>=8 (f4 bit11 = q bit3 set)
__device__ __forceinline__ void stv8hi(ulonglong2* s4, int base, const ulonglong2 v[16]) {
    #pragma unroll
    for (int q = 8; q < 16; q++) s4[base ^ swzF(q << 8)] = v[q];
}
// P6' window: q bits -> f4 bits {1,2,5,6} (amp bits 3,4,7,8)
__device__ __forceinline__ int off6(int q) {
    return ((q & 3) << 1) | ((q >> 2) << 5);
}

// ---------------------------------------------------------------------------
// Main kernel: 1 CTA/row, 7 passes. Dead cone: b13=1 from P4,
// b13=1 & b10=1 (quarter) from P6' on. 2 CTAs/SM.
// ---------------------------------------------------------------------------
__global__ void __launch_bounds__(TPB, 2) qnn_main(const float* __restrict__ in,
                                                   float* __restrict__ out) {
    extern __shared__ float sm[];
    ulonglong2* s4 = (ulonglong2*)sm;            // 16384 floats state
    ull*   sGp  = (ull*)(sm + DIM);              // 448 splatted gate coeffs
    float* sGs  = sm + DIM + 896;                // 448 scalar gate coeffs
    float* red  = sGs + 448;
    float* pinv = red + 8;
    const int t = threadIdx.x;
    const int b = blockIdx.x;

    for (int x = t; x < 448; x += TPB) {
        float g = d_G[x];
        sGs[x] = g;
        sGp[x] = pk2(g, g);
    }

    // ---- P1: global load in tile order + sum-of-squares
    const ulonglong2* g4 = (const ulonglong2*)(in + (size_t)b * DIM);
    ulonglong2 v[16];
    ull ssp = 0ull;
    #pragma unroll
    for (int q = 0; q < 16; q++) {
        v[q] = g4[(t << 4) | q];
        ssp = f2fma(v[q].x, v[q].x, ssp);
        ssp = f2fma(v[q].y, v[q].y, ssp);
    }
    float s0, s1; up2(ssp, s0, s1);
    float ss = s0 + s1;
    #pragma unroll
    for (int o = 16; o; o >>= 1) ss += __shfl_xor_sync(0xffffffffu, ss, o);
    if ((t & 31) == 0) red[t >> 5] = ss;
    __syncthreads();                      // B1: gate tables + red
    if (t == 0) {
        float tot = 0.f;
        #pragma unroll
        for (int k = 0; k < 8; k++) tot += red[k];
        pinv[0] = 1.0f / tot;             // read in P7, ordered by B2..B7
    }

    // P1 gates, tile {0,1,2,3,4,5}: e0,e1,e2,o0,o1,f0,f1,p0  (8 gates)
    { G16  g = ldGm(sGs, 0);  op_vecS(g, v); }         // e0 (1,0)
    { G16P g = ldGp(sGp, 1);  op_qlowP(g, v); }        // e1 (3,2)
    { G16P g = ldGp(sGp, 2);  op_qhighP(g, v); }       // e2 (5,4)
    { G16P g = ldGp(sGp, 7);  op_g21P(g, v); }         // o0 (2,1)
    { G16P g = ldGp(sGp, 8);  op_g43P(g, v); }         // o1 (4,3)
    { G16  g = ldGm(sGs, 14); op_vecS(g, v); }         // f0 (1,0)
    { G16P g = ldGp(sGp, 15); op_qlowP(g, v); }        // f1 (3,2)
    { G16P g = ldGp(sGp, 21); op_g21P(g, v); }         // p0 (2,1)
    { int base = swzF(t << 4); stvS<0>(s4, base, v); }
    __syncthreads();                      // B2

    // ---- P2, window f4{4..7}: e3,e4,o3
    { int base = swzF((t & 15) | ((t >> 4) << 8));
      ldvS<4>(s4, base, v);
      { G16P g = ldGp(sGp, 3);  op_qlowP(g, v); }      // e3 (7,6)
      { G16P g = ldGp(sGp, 4);  op_qhighP(g, v); }     // e4 (9,8)
      { G16P g = ldGp(sGp, 10); op_g43P(g, v); }       // o3 (8,7)
      stvS<4>(s4, base, v); }
    __syncthreads();                      // B3

    // ---- P3, window f4{8..11}: e5,e6,o5,f6; store bit13=1 half only
    { int base = swzF(t);
      ldvS<8>(s4, base, v);
      { G16P g = ldGp(sGp, 5);  op_qlowP(g, v); }      // e5 (11,10)
      { G16P g = ldGp(sGp, 6);  op_qhighP(g, v); }     // e6 (13,12)
      { G16P g = ldGp(sGp, 12); op_g43P(g, v); }       // o5 (12,11)
      { G16P g = ldGp(sGp, 20); op_qhighP(g, v); }     // f6 (13,12)
      stv8hi(s4, base, v); }
    __syncthreads();                      // B4

    // ---- P4, window f4{2..5} (amp 4..7): o2,f2,f3,p2 — bit13=1 only
    if (t >= 128) {
      int base = swzF((t & 3) | ((t >> 2) << 6));      // f4 bit11 = t bit7 = 1
      ldvS<2>(s4, base, v);
      { G16P g = ldGp(sGp, 9);  op_g43P(g, v); }       // o2 (6,5)
      { G16P g = ldGp(sGp, 16); op_qlowP(g, v); }      // f2 (5,4)
      { G16P g = ldGp(sGp, 17); op_qhighP(g, v); }     // f3 (7,6)
      { G16P g = ldGp(sGp, 23); op_g43P(g, v); }       // p2 (6,5)
      stvS<2>(s4, base, v);
    }
    __syncthreads();                      // B5

    // ---- P5, window f4{6..9} (amp 8..11): o4,f4,f5,p4(rows 2,3) — bit13=1
    //      store only q&4 half (amp b10=1); b10=0 outputs dead downstream
    if (t >= 128) {
      int base = swzF((t & 63) | ((t >> 6) << 10));    // f4 bit11 = t bit7 = 1
      ldvS<6>(s4, base, v);
      { G16P g = ldGp(sGp, 11); op_g43P(g, v); }       // o4 (10,9)
      { G16P g = ldGp(sGp, 18); op_qlowP(g, v); }      // f4 (9,8)
      { G16P g = ldGp(sGp, 19); op_qhighP(g, v); }     // f5 (11,10)
      { G16P g = ldGp(sGp, 25); op_g43P_hi(g, v); }    // p4 (10,9), rows m=2,3
      #pragma unroll
      for (int q = 0; q < 16; q++)
          if (q & 4) s4[base ^ swzF(q << 6)] = v[q];
    }
    __syncthreads();                      // B6

    // ---- P6', quarter cone {f4 b11=1, b8=1}: p1 (4,3) + p3 (8,7)
    //      window q -> f4 {1,2,5,6} (amp 3,4,7,8); base t -> f4 {0,3,4,7,9,10}
    if (t < 64) {
        int base = swzF((t & 1) | (((t >> 1) & 3) << 3) | (((t >> 3) & 1) << 7)
                        | (((t >> 4) & 3) << 9) | (1 << 8) | (1 << 11));
        #pragma unroll
        for (int q = 0; q < 16; q++) v[q] = s4[base ^ swzF(off6(q))];
        { G16P g = ldGp(sGp, 22); op_qlowP(g, v); }    // p1 (4,3) = q bits (1,0)
        { G16P g = ldGp(sGp, 24); op_qhighP(g, v); }   // p3 (8,7) = q bits (3,2)
        #pragma unroll
        for (int q = 0; q < 16; q++) s4[base ^ swzF(off6(q))] = v[q];
    }
    __syncthreads();                      // B7

    // ---- P7: p5 (12,11) row m=3 only + output (amps j >= 15384)
    if (t >= 6) {
        ulonglong2 v0 = s4[swzF(2304 + t)];   // (f4 b10,b9) = amp (b12,b11)=(0,0)
        ulonglong2 v1 = s4[swzF(2816 + t)];   // (0,1)
        ulonglong2 v2 = s4[swzF(3328 + t)];   // (1,0)
        ulonglong2 v3 = s4[swzF(3840 + t)];   // (1,1)
        G16P g = ldGp(sGp, 26);                        // p5
        ull dx = f2fma(g.g[15], v3.x, f2fma(g.g[14], v2.x,
                 f2fma(g.g[13], v1.x, f2mul(g.g[12], v0.x))));
        ull dy = f2fma(g.g[15], v3.y, f2fma(g.g[14], v2.y,
                 f2fma(g.g[13], v1.y, f2mul(g.g[12], v0.y))));
        float inv = pinv[0];
        ull invp = pk2(inv, inv);
        ulonglong2 r;
        r.x = f2mul(f2mul(dx, dx), invp);
        r.y = f2mul(f2mul(dy, dy), invp);
        *(ulonglong2*)(out + (size_t)b * OUTN + 4 * t - 24) = r;
    }
}

extern "C" void kernel_launch(void* const* d_in, const int* in_sizes, int n_in,
                              void* d_out, int out_size) {
    const float* in   = (const float*)d_in[0];
    const float* w    = (const float*)d_in[1];
    const float* bias = (const float*)d_in[2];
    float* out = (float*)d_out;
    int B = in_sizes[0] / DIM;   // 512

    const int smem_bytes = (DIM + 896 + 448 + 8 + 8) * (int)sizeof(float);  // ~71 KB
    cudaFuncSetAttribute(qnn_main, cudaFuncAttributeMaxDynamicSharedMemorySize, smem_bytes);

    qnn_prep<<<1, 32>>>(w, bias);
    qnn_main<<<B, TPB, smem_bytes>>>(in, out);
}

// round 13
// speedup vs baseline: 1.1935x; 1.0960x over previous
#include <cuda_runtime.h>

#define DIM 16384
#define OUTN 1000
#define TPB 256

typedef unsigned long long ull;

// ---------------------------------------------------------------------------
// GF(2)-linear swizzle (R6, verified): bank bit2 ^= b3^b6, bit1 ^= b4, bit0 ^= b5
// ---------------------------------------------------------------------------
__host__ __device__ __forceinline__ constexpr int swzF(int P) {
    return P ^ (((((P >> 3) ^ (P >> 6)) & 1) << 2)
             |  ((((P >> 4)) & 1) << 1)
             |  (((P >> 5)) & 1));
}

// ---------------------------------------------------------------------------
// Packed f32x2 helpers (FFMA2 — ptxas never emits from C++)
// ---------------------------------------------------------------------------
__device__ __forceinline__ ull f2mul(ull a, ull b) {
    ull d; asm("mul.rn.f32x2 %0, %1, %2;" : "=l"(d) : "l"(a), "l"(b)); return d;
}
__device__ __forceinline__ ull f2fma(ull a, ull b, ull c) {
    ull d; asm("fma.rn.f32x2 %0, %1, %2, %3;" : "=l"(d) : "l"(a), "l"(b), "l"(c)); return d;
}
__device__ __forceinline__ void up2(ull a, float& x, float& y) {
    asm("mov.b64 {%0, %1}, %2;" : "=f"(x), "=f"(y) : "l"(a));
}
__device__ __forceinline__ ull pk2(float x, float y) {
    ull a; asm("mov.b64 %0, {%1, %2};" : "=l"(a) : "f"(x), "f"(y)); return a;
}

struct G16P { ull g[16]; };
struct C8   { ull c[8]; };

// vectorized coefficient loads (LDS.128)
__device__ __forceinline__ G16P ldGp(const ull* sGp, int i) {
    G16P r;
    const ulonglong2* p = (const ulonglong2*)(sGp + i * 16);
    #pragma unroll
    for (int x = 0; x < 8; x++) {
        ulonglong2 u = p[x];
        r.g[2*x] = u.x; r.g[2*x+1] = u.y;
    }
    return r;
}
__device__ __forceinline__ C8 ldCv(const ull* sCv, int i) {
    C8 r;
    const ulonglong2* p = (const ulonglong2*)(sCv + i * 8);
    #pragma unroll
    for (int x = 0; x < 4; x++) {
        ulonglong2 u = p[x];
        r.c[2*x] = u.x; r.c[2*x+1] = u.y;
    }
    return r;
}

__device__ __forceinline__ void gate4p(const G16P& G, ull& a, ull& b, ull& c, ull& d) {
    ull x = a, y = b, z = c, w = d;
    a = f2fma(G.g[3],  w, f2fma(G.g[2],  z, f2fma(G.g[1],  y, f2mul(G.g[0],  x))));
    b = f2fma(G.g[7],  w, f2fma(G.g[6],  z, f2fma(G.g[5],  y, f2mul(G.g[4],  x))));
    c = f2fma(G.g[11], w, f2fma(G.g[10], z, f2fma(G.g[9],  y, f2mul(G.g[8],  x))));
    d = f2fma(G.g[15], w, f2fma(G.g[14], z, f2fma(G.g[13], y, f2mul(G.g[12], x))));
}
// rows 2,3 only (outputs c,d); a,b positions left stale (dead downstream)
__device__ __forceinline__ void gate4p_hi(const G16P& G, ull x, ull y, ull& z, ull& w) {
    ull zi = z, wi = w;
    z = f2fma(G.g[11], wi, f2fma(G.g[10], zi, f2fma(G.g[9],  y, f2mul(G.g[8],  x))));
    w = f2fma(G.g[15], wi, f2fma(G.g[14], zi, f2fma(G.g[13], y, f2mul(G.g[12], x))));
}

// gate on amp bits (1,0), fully packed via lane-pair coefficients:
//   X=(a0,a1), Y=(a2,a3); X' = c0*X + c1*Xs + c2*Y + c3*Ys, Y' = c4..c7 likewise
__device__ __forceinline__ void op_vec2P(const C8& C, ulonglong2 v[16]) {
    #pragma unroll
    for (int q = 0; q < 16; q++) {
        ull X = v[q].x, Y = v[q].y;
        float x0, x1, y0, y1;
        up2(X, x0, x1); up2(Y, y0, y1);
        ull Xs = pk2(x1, x0), Ys = pk2(y1, y0);
        v[q].x = f2fma(C.c[3], Ys, f2fma(C.c[2], Y, f2fma(C.c[1], Xs, f2mul(C.c[0], X))));
        v[q].y = f2fma(C.c[7], Ys, f2fma(C.c[6], Y, f2fma(C.c[5], Xs, f2mul(C.c[4], X))));
    }
}
// gate on q bits (1,0)
__device__ __forceinline__ void op_qlowP(const G16P& G, ulonglong2 v[16]) {
    #pragma unroll
    for (int h = 0; h < 16; h += 4) {
        gate4p(G, v[h].x, v[h+1].x, v[h+2].x, v[h+3].x);
        gate4p(G, v[h].y, v[h+1].y, v[h+2].y, v[h+3].y);
    }
}
// gate on q bits (3,2)
__device__ __forceinline__ void op_qhighP(const G16P& G, ulonglong2 v[16]) {
    #pragma unroll
    for (int j = 0; j < 4; j++) {
        gate4p(G, v[j].x, v[j+4].x, v[j+8].x, v[j+12].x);
        gate4p(G, v[j].y, v[j+4].y, v[j+8].y, v[j+12].y);
    }
}
// gate on q bits (3,2), output rows m=2,3 only (q bit3=1 rows)
__device__ __forceinline__ void op_qhighP_hi(const G16P& G, ulonglong2 v[16]) {
    #pragma unroll
    for (int j = 0; j < 4; j++) {
        gate4p_hi(G, v[j].x, v[j+4].x, v[j+8].x, v[j+12].x);
        gate4p_hi(G, v[j].y, v[j+4].y, v[j+8].y, v[j+12].y);
    }
}
// gate on q bits (2,1)
__device__ __forceinline__ void op_g43P(const G16P& G, ulonglong2 v[16]) {
    #pragma unroll
    for (int j3 = 0; j3 < 2; j3++)
        #pragma unroll
        for (int j0 = 0; j0 < 2; j0++) {
            int b0 = j0 + 8 * j3;
            gate4p(G, v[b0].x, v[b0+2].x, v[b0+4].x, v[b0+6].x);
            gate4p(G, v[b0].y, v[b0+2].y, v[b0+4].y, v[b0+6].y);
        }
}
// gate on q bits (2,1), output rows m=2,3 only
__device__ __forceinline__ void op_g43P_hi(const G16P& G, ulonglong2 v[16]) {
    #pragma unroll
    for (int j3 = 0; j3 < 2; j3++)
        #pragma unroll
        for (int j0 = 0; j0 < 2; j0++) {
            int b0 = j0 + 8 * j3;
            gate4p_hi(G, v[b0].x, v[b0+2].x, v[b0+4].x, v[b0+6].x);
            gate4p_hi(G, v[b0].y, v[b0+2].y, v[b0+4].y, v[b0+6].y);
        }
}
// gate hi = q bit0, lo = amp bit1 (.x/.y halves)
__device__ __forceinline__ void op_g21P(const G16P& G, ulonglong2 v[16]) {
    #pragma unroll
    for (int h = 0; h < 16; h += 2)
        gate4p(G, v[h].x, v[h].y, v[h+1].x, v[h+1].y);
}

// q placed at f4-index bits [S, S+3]; per-q offset is a compile-time XOR
template<int S>
__device__ __forceinline__ void ldvS(const ulonglong2* s4, int base, ulonglong2 v[16]) {
    #pragma unroll
    for (int q = 0; q < 16; q++) v[q] = s4[base ^ swzF(q << S)];
}
template<int S>
__device__ __forceinline__ void stvS(ulonglong2* s4, int base, const ulonglong2 v[16]) {
    #pragma unroll
    for (int q = 0; q < 16; q++) s4[base ^ swzF(q << S)] = v[q];
}
// P3 store: only q>=8 (amp bit13 = q bit3 set)
__device__ __forceinline__ void stv8hi(ulonglong2* s4, int base, const ulonglong2 v[16]) {
    #pragma unroll
    for (int q = 8; q < 16; q++) s4[base ^ swzF(q << 8)] = v[q];
}
// P6' window: q bits -> f4 bits {1,2,5,6} (amp bits 3,4,7,8)
__device__ __forceinline__ int off6(int q) {
    return ((q & 3) << 1) | ((q >> 2) << 5);
}

// ---------------------------------------------------------------------------
// Main kernel: single launch (gate prep fused), 7 passes.
// Dead cone: b13=1 from P4, (b13,b10)=(1,1) from P6'. 2 CTAs/SM.
// ---------------------------------------------------------------------------
__global__ void __launch_bounds__(TPB, 2) qnn_main(const float* __restrict__ in,
                                                   const float* __restrict__ wts,
                                                   const float* __restrict__ bias,
                                                   float* __restrict__ out) {
    extern __shared__ float sm[];
    ulonglong2* s4 = (ulonglong2*)sm;            // 16384 floats state
    ull*   sGp  = (ull*)(sm + DIM);              // 448 ull splatted gate coeffs
    ull*   sCv  = (ull*)(sm + DIM + 896);        // 16 ull lane-pair coeffs (e0,f0)
    float* red  = sm + DIM + 896 + 32;
    float* pinv = red + 8;
    const int t = threadIdx.x;
    const int b = blockIdx.x;

    // ---- In-kernel gate prep: threads 0..25 build the 26 fused gates.
    if (t < 26) {
        int g = t;
        int stage, p;
        if (g < 7)       { stage = 0; p = g; }
        else if (g < 13) { stage = 1; p = g - 7; }
        else if (g < 20) { stage = 2; p = g - 13; }
        else             { stage = 3; p = g - 20; }
        int l = stage >> 1;
        int par = stage & 1;
        int i = par ? (11 - 2 * p) : (12 - 2 * p);

        float thH = 0.5f * wts[l * 26 + i * 2 + 0];
        float thL = 0.5f * wts[l * 26 + i * 2 + 1];
        float A[4] = { cosf(thH), -sinf(thH), sinf(thH), cosf(thH) };
        float B[4] = { cosf(thL), -sinf(thL), sinf(thL), cosf(thL) };
        float G[16];
        for (int mp = 0; mp < 4; mp++)
            for (int m = 0; m < 4; m++) {
                float v = A[(mp >> 1) * 2 + (m >> 1)] * B[(mp & 1) * 2 + (m & 1)];
                G[mp * 4 + m] = (m == 3) ? -v : v;   // CZ applied first
            }
        if (stage == 0) {
            float bH = 0.5f * bias[i], bL = 0.5f * bias[i + 1];
            float Ab[4] = { cosf(bH), -sinf(bH), sinf(bH), cosf(bH) };
            float Bb[4] = { cosf(bL), -sinf(bL), sinf(bL), cosf(bL) };
            float Gb[16];
            for (int mp = 0; mp < 4; mp++)
                for (int m = 0; m < 4; m++)
                    Gb[mp * 4 + m] = Ab[(mp >> 1) * 2 + (m >> 1)] * Bb[(mp & 1) * 2 + (m & 1)];
            float GG[16];
            for (int a = 0; a < 4; a++)
                for (int c = 0; c < 4; c++) {
                    float s = 0.f;
                    for (int k = 0; k < 4; k++) s += G[a * 4 + k] * Gb[k * 4 + c];
                    GG[a * 4 + c] = s;               // apply bias first
                }
            for (int x = 0; x < 16; x++) G[x] = GG[x];
        }
        int gi = stage * 7 + p;
        for (int x = 0; x < 16; x++) sGp[gi * 16 + x] = pk2(G[x], G[x]);
        if (gi == 0 || gi == 14) {
            ull* c = sCv + (gi == 14 ? 8 : 0);
            c[0] = pk2(G[0],  G[5]);  c[1] = pk2(G[1],  G[4]);
            c[2] = pk2(G[2],  G[7]);  c[3] = pk2(G[3],  G[6]);
            c[4] = pk2(G[8],  G[13]); c[5] = pk2(G[9],  G[12]);
            c[6] = pk2(G[10], G[15]); c[7] = pk2(G[11], G[14]);
        }
    }

    // ---- P1: global load in tile order + sum-of-squares
    const ulonglong2* g4 = (const ulonglong2*)(in + (size_t)b * DIM);
    ulonglong2 v[16];
    ull ssp = 0ull;
    #pragma unroll
    for (int q = 0; q < 16; q++) {
        v[q] = g4[(t << 4) | q];
        ssp = f2fma(v[q].x, v[q].x, ssp);
        ssp = f2fma(v[q].y, v[q].y, ssp);
    }
    float s0, s1; up2(ssp, s0, s1);
    float ss = s0 + s1;
    #pragma unroll
    for (int o = 16; o; o >>= 1) ss += __shfl_xor_sync(0xffffffffu, ss, o);
    if ((t & 31) == 0) red[t >> 5] = ss;
    __syncthreads();                      // B1: gate tables + red
    if (t == 0) {
        float tot = 0.f;
        #pragma unroll
        for (int k = 0; k < 8; k++) tot += red[k];
        pinv[0] = 1.0f / tot;             // read in P7, ordered by B2..B7
    }

    // P1 gates, tile {0,1,2,3,4,5}: e0,e1,e2,o0,o1,f0,f1,p0  (8 gates)
    { C8   c = ldCv(sCv, 0);  op_vec2P(c, v); }        // e0 (1,0) packed
    { G16P g = ldGp(sGp, 1);  op_qlowP(g, v); }        // e1 (3,2)
    { G16P g = ldGp(sGp, 2);  op_qhighP(g, v); }       // e2 (5,4)
    { G16P g = ldGp(sGp, 7);  op_g21P(g, v); }         // o0 (2,1)
    { G16P g = ldGp(sGp, 8);  op_g43P(g, v); }         // o1 (4,3)
    { C8   c = ldCv(sCv, 1);  op_vec2P(c, v); }        // f0 (1,0) packed
    { G16P g = ldGp(sGp, 15); op_qlowP(g, v); }        // f1 (3,2)
    { G16P g = ldGp(sGp, 21); op_g21P(g, v); }         // p0 (2,1)
    { int base = swzF(t << 4); stvS<0>(s4, base, v); }
    __syncthreads();                      // B2

    // ---- P2, window f4{4..7}: e3,e4,o3
    { int base = swzF((t & 15) | ((t >> 4) << 8));
      ldvS<4>(s4, base, v);
      { G16P g = ldGp(sGp, 3);  op_qlowP(g, v); }      // e3 (7,6)
      { G16P g = ldGp(sGp, 4);  op_qhighP(g, v); }     // e4 (9,8)
      { G16P g = ldGp(sGp, 10); op_g43P(g, v); }       // o3 (8,7)
      stvS<4>(s4, base, v); }
    __syncthreads();                      // B3

    // ---- P3, window f4{8..11}: e5,e6,o5,f6(rows 2,3); store b13=1 half only
    { int base = swzF(t);
      ldvS<8>(s4, base, v);
      { G16P g = ldGp(sGp, 5);  op_qlowP(g, v); }      // e5 (11,10)
      { G16P g = ldGp(sGp, 6);  op_qhighP(g, v); }     // e6 (13,12)
      { G16P g = ldGp(sGp, 12); op_g43P(g, v); }       // o5 (12,11)
      { G16P g = ldGp(sGp, 20); op_qhighP_hi(g, v); }  // f6 (13,12), rows m=2,3
      stv8hi(s4, base, v); }
    __syncthreads();                      // B4

    // ---- P4, window f4{2..5} (amp 4..7): o2,f2,f3,p2 — b13=1 only
    if (t >= 128) {
      int base = swzF((t & 3) | ((t >> 2) << 6));      // f4 bit11 = t bit7 = 1
      ldvS<2>(s4, base, v);
      { G16P g = ldGp(sGp, 9);  op_g43P(g, v); }       // o2 (6,5)
      { G16P g = ldGp(sGp, 16); op_qlowP(g, v); }      // f2 (5,4)
      { G16P g = ldGp(sGp, 17); op_qhighP(g, v); }     // f3 (7,6)
      { G16P g = ldGp(sGp, 23); op_g43P(g, v); }       // p2 (6,5)
      stvS<2>(s4, base, v);
    }
    __syncthreads();                      // B5

    // ---- P5, window f4{6..9} (amp 8..11): o4,f4,f5,p4(rows 2,3) — b13=1
    //      store only q&4 half (amp b10=1); b10=0 outputs dead downstream
    if (t >= 128) {
      int base = swzF((t & 63) | ((t >> 6) << 10));    // f4 bit11 = t bit7 = 1
      ldvS<6>(s4, base, v);
      { G16P g = ldGp(sGp, 11); op_g43P(g, v); }       // o4 (10,9)
      { G16P g = ldGp(sGp, 18); op_qlowP(g, v); }      // f4 (9,8)
      { G16P g = ldGp(sGp, 19); op_qhighP(g, v); }     // f5 (11,10)
      { G16P g = ldGp(sGp, 25); op_g43P_hi(g, v); }    // p4 (10,9), rows m=2,3
      #pragma unroll
      for (int q = 0; q < 16; q++)
          if (q & 4) s4[base ^ swzF(q << 6)] = v[q];
    }
    __syncthreads();                      // B6

    // ---- P6', quarter cone {f4 b11=1, b8=1}: p1 (4,3) + p3 (8,7)
    if (t < 64) {
        int base = swzF((t & 1) | (((t >> 1) & 3) << 3) | (((t >> 3) & 1) << 7)
                        | (((t >> 4) & 3) << 9) | (1 << 8) | (1 << 11));
        #pragma unroll
        for (int q = 0; q < 16; q++) v[q] = s4[base ^ swzF(off6(q))];
        { G16P g = ldGp(sGp, 22); op_qlowP(g, v); }    // p1 (4,3) = q bits (1,0)
        { G16P g = ldGp(sGp, 24); op_qhighP(g, v); }   // p3 (8,7) = q bits (3,2)
        #pragma unroll
        for (int q = 0; q < 16; q++) s4[base ^ swzF(off6(q))] = v[q];
    }
    __syncthreads();                      // B7

    // ---- P7: p5 (12,11) row m=3 only + output (amps j >= 15384)
    if (t >= 6) {
        ulonglong2 v0 = s4[swzF(2304 + t)];   // amp (b12,b11)=(0,0)
        ulonglong2 v1 = s4[swzF(2816 + t)];   // (0,1)
        ulonglong2 v2 = s4[swzF(3328 + t)];   // (1,0)
        ulonglong2 v3 = s4[swzF(3840 + t)];   // (1,1)
        G16P g = ldGp(sGp, 26);                        // p5
        ull dx = f2fma(g.g[15], v3.x, f2fma(g.g[14], v2.x,
                 f2fma(g.g[13], v1.x, f2mul(g.g[12], v0.x))));
        ull dy = f2fma(g.g[15], v3.y, f2fma(g.g[14], v2.y,
                 f2fma(g.g[13], v1.y, f2mul(g.g[12], v0.y))));
        float inv = pinv[0];
        ull invp = pk2(inv, inv);
        ulonglong2 r;
        r.x = f2mul(f2mul(dx, dx), invp);
        r.y = f2mul(f2mul(dy, dy), invp);
        *(ulonglong2*)(out + (size_t)b * OUTN + 4 * t - 24) = r;
    }
}

extern "C" void kernel_launch(void* const* d_in, const int* in_sizes, int n_in,
                              void* d_out, int out_size) {
    const float* in   = (const float*)d_in[0];
    const float* w    = (const float*)d_in[1];
    const float* bias = (const float*)d_in[2];
    float* out = (float*)d_out;
    int B = in_sizes[0] / DIM;   // 512

    const int smem_bytes = (DIM + 896 + 32 + 8 + 8) * (int)sizeof(float);  // ~68 KB
    cudaFuncSetAttribute(qnn_main, cudaFuncAttributeMaxDynamicSharedMemorySize, smem_bytes);

    qnn_main<<<B, TPB, smem_bytes>>>(in, w, bias, out);
}

// round 16
// speedup vs baseline: 1.2023x; 1.0073x over previous
#include <cuda_runtime.h>

#define DIM 16384
#define OUTN 1000
#define TPB 256

typedef unsigned long long ull;

// ---------------------------------------------------------------------------
// GF(2)-linear swizzle (R6, verified): bank bit2 ^= b3^b6, bit1 ^= b4, bit0 ^= b5
// ---------------------------------------------------------------------------
__host__ __device__ __forceinline__ constexpr int swzF(int P) {
    return P ^ (((((P >> 3) ^ (P >> 6)) & 1) << 2)
             |  ((((P >> 4)) & 1) << 1)
             |  (((P >> 5)) & 1));
}

// ---------------------------------------------------------------------------
// Packed f32x2 helpers (FFMA2 — ptxas never emits from C++)
// ---------------------------------------------------------------------------
__device__ __forceinline__ ull f2mul(ull a, ull b) {
    ull d; asm("mul.rn.f32x2 %0, %1, %2;" : "=l"(d) : "l"(a), "l"(b)); return d;
}
__device__ __forceinline__ ull f2fma(ull a, ull b, ull c) {
    ull d; asm("fma.rn.f32x2 %0, %1, %2, %3;" : "=l"(d) : "l"(a), "l"(b), "l"(c)); return d;
}
__device__ __forceinline__ void up2(ull a, float& x, float& y) {
    asm("mov.b64 {%0, %1}, %2;" : "=f"(x), "=f"(y) : "l"(a));
}
__device__ __forceinline__ ull pk2(float x, float y) {
    ull a; asm("mov.b64 %0, {%1, %2};" : "=l"(a) : "f"(x), "f"(y)); return a;
}

struct G16P { ull g[16]; };
struct C8   { ull c[8]; };

// vectorized coefficient loads (LDS.128)
__device__ __forceinline__ G16P ldGp(const ull* sGp, int i) {
    G16P r;
    const ulonglong2* p = (const ulonglong2*)(sGp + i * 16);
    #pragma unroll
    for (int x = 0; x < 8; x++) {
        ulonglong2 u = p[x];
        r.g[2*x] = u.x; r.g[2*x+1] = u.y;
    }
    return r;
}
__device__ __forceinline__ C8 ldCv(const ull* sCv, int i) {
    C8 r;
    const ulonglong2* p = (const ulonglong2*)(sCv + i * 8);
    #pragma unroll
    for (int x = 0; x < 4; x++) {
        ulonglong2 u = p[x];
        r.c[2*x] = u.x; r.c[2*x+1] = u.y;
    }
    return r;
}

__device__ __forceinline__ void gate4p(const G16P& G, ull& a, ull& b, ull& c, ull& d) {
    ull x = a, y = b, z = c, w = d;
    a = f2fma(G.g[3],  w, f2fma(G.g[2],  z, f2fma(G.g[1],  y, f2mul(G.g[0],  x))));
    b = f2fma(G.g[7],  w, f2fma(G.g[6],  z, f2fma(G.g[5],  y, f2mul(G.g[4],  x))));
    c = f2fma(G.g[11], w, f2fma(G.g[10], z, f2fma(G.g[9],  y, f2mul(G.g[8],  x))));
    d = f2fma(G.g[15], w, f2fma(G.g[14], z, f2fma(G.g[13], y, f2mul(G.g[12], x))));
}
// rows 2,3 only (outputs c,d); a,b positions left stale (dead downstream)
__device__ __forceinline__ void gate4p_hi(const G16P& G, ull x, ull y, ull& z, ull& w) {
    ull zi = z, wi = w;
    z = f2fma(G.g[11], wi, f2fma(G.g[10], zi, f2fma(G.g[9],  y, f2mul(G.g[8],  x))));
    w = f2fma(G.g[15], wi, f2fma(G.g[14], zi, f2fma(G.g[13], y, f2mul(G.g[12], x))));
}

// gate on amp bits (1,0), fully packed via lane-pair coefficients:
//   X=(a0,a1), Y=(a2,a3); X' = c0*X + c1*Xs + c2*Y + c3*Ys, Y' = c4..c7 likewise
__device__ __forceinline__ void op_vec2P(const C8& C, ulonglong2 v[16]) {
    #pragma unroll
    for (int q = 0; q < 16; q++) {
        ull X = v[q].x, Y = v[q].y;
        float x0, x1, y0, y1;
        up2(X, x0, x1); up2(Y, y0, y1);
        ull Xs = pk2(x1, x0), Ys = pk2(y1, y0);
        v[q].x = f2fma(C.c[3], Ys, f2fma(C.c[2], Y, f2fma(C.c[1], Xs, f2mul(C.c[0], X))));
        v[q].y = f2fma(C.c[7], Ys, f2fma(C.c[6], Y, f2fma(C.c[5], Xs, f2mul(C.c[4], X))));
    }
}
// gate on q bits (1,0)
__device__ __forceinline__ void op_qlowP(const G16P& G, ulonglong2 v[16]) {
    #pragma unroll
    for (int h = 0; h < 16; h += 4) {
        gate4p(G, v[h].x, v[h+1].x, v[h+2].x, v[h+3].x);
        gate4p(G, v[h].y, v[h+1].y, v[h+2].y, v[h+3].y);
    }
}
// gate on q bits (3,2)
__device__ __forceinline__ void op_qhighP(const G16P& G, ulonglong2 v[16]) {
    #pragma unroll
    for (int j = 0; j < 4; j++) {
        gate4p(G, v[j].x, v[j+4].x, v[j+8].x, v[j+12].x);
        gate4p(G, v[j].y, v[j+4].y, v[j+8].y, v[j+12].y);
    }
}
// gate on q bits (3,2), output rows m=2,3 only (q bit3=1 rows)
__device__ __forceinline__ void op_qhighP_hi(const G16P& G, ulonglong2 v[16]) {
    #pragma unroll
    for (int j = 0; j < 4; j++) {
        gate4p_hi(G, v[j].x, v[j+4].x, v[j+8].x, v[j+12].x);
        gate4p_hi(G, v[j].y, v[j+4].y, v[j+8].y, v[j+12].y);
    }
}
// gate on q bits (2,1)
__device__ __forceinline__ void op_g43P(const G16P& G, ulonglong2 v[16]) {
    #pragma unroll
    for (int j3 = 0; j3 < 2; j3++)
        #pragma unroll
        for (int j0 = 0; j0 < 2; j0++) {
            int b0 = j0 + 8 * j3;
            gate4p(G, v[b0].x, v[b0+2].x, v[b0+4].x, v[b0+6].x);
            gate4p(G, v[b0].y, v[b0+2].y, v[b0+4].y, v[b0+6].y);
        }
}
// gate on q bits (2,1), output rows m=2,3 only
__device__ __forceinline__ void op_g43P_hi(const G16P& G, ulonglong2 v[16]) {
    #pragma unroll
    for (int j3 = 0; j3 < 2; j3++)
        #pragma unroll
        for (int j0 = 0; j0 < 2; j0++) {
            int b0 = j0 + 8 * j3;
            gate4p_hi(G, v[b0].x, v[b0+2].x, v[b0+4].x, v[b0+6].x);
            gate4p_hi(G, v[b0].y, v[b0+2].y, v[b0+4].y, v[b0+6].y);
        }
}
// gate hi = q bit0, lo = amp bit1 (.x/.y halves)
__device__ __forceinline__ void op_g21P(const G16P& G, ulonglong2 v[16]) {
    #pragma unroll
    for (int h = 0; h < 16; h += 2)
        gate4p(G, v[h].x, v[h].y, v[h+1].x, v[h+1].y);
}

// q placed at f4-index bits [S, S+3]; per-q offset is a compile-time XOR
template<int S>
__device__ __forceinline__ void ldvS(const ulonglong2* s4, int base, ulonglong2 v[16]) {
    #pragma unroll
    for (int q = 0; q < 16; q++) v[q] = s4[base ^ swzF(q << S)];
}
template<int S>
__device__ __forceinline__ void stvS(ulonglong2* s4, int base, const ulonglong2 v[16]) {
    #pragma unroll
    for (int q = 0; q < 16; q++) s4[base ^ swzF(q << S)] = v[q];
}
// P3 store: only q>=8 (amp bit13 = q bit3 set)
__device__ __forceinline__ void stv8hi(ulonglong2* s4, int base, const ulonglong2 v[16]) {
    #pragma unroll
    for (int q = 8; q < 16; q++) s4[base ^ swzF(q << 8)] = v[q];
}
// P6' window: q bits -> f4 bits {1,2,5,6} (amp bits 3,4,7,8)
__device__ __forceinline__ int off6(int q) {
    return ((q & 3) << 1) | ((q >> 2) << 5);
}

// ---------------------------------------------------------------------------
// Main kernel: single launch (gate prep fused), 7 passes.
// Dead cone: b13=1 from P4, (b13,b10)=(1,1) from P6'. 2 CTAs/SM.
// ---------------------------------------------------------------------------
__global__ void __launch_bounds__(TPB, 2) qnn_main(const float* __restrict__ in,
                                                   const float* __restrict__ wts,
                                                   const float* __restrict__ bias,
                                                   float* __restrict__ out) {
    extern __shared__ float sm[];
    ulonglong2* s4 = (ulonglong2*)sm;            // 16384 floats state
    ull*   sGp  = (ull*)(sm + DIM);              // 448 ull splatted gate coeffs
    ull*   sCv  = (ull*)(sm + DIM + 896);        // 16 ull lane-pair coeffs (e0,f0)
    float* red  = sm + DIM + 896 + 32;
    float* pinv = red + 8;
    const int t = threadIdx.x;
    const int b = blockIdx.x;

    // ---- In-kernel gate prep: threads 0..25 build the 26 fused gates.
    if (t < 26) {
        int g = t;
        int stage, p;
        if (g < 7)       { stage = 0; p = g; }
        else if (g < 13) { stage = 1; p = g - 7; }
        else if (g < 20) { stage = 2; p = g - 13; }
        else             { stage = 3; p = g - 20; }
        int l = stage >> 1;
        int par = stage & 1;
        int i = par ? (11 - 2 * p) : (12 - 2 * p);

        float thH = 0.5f * wts[l * 26 + i * 2 + 0];
        float thL = 0.5f * wts[l * 26 + i * 2 + 1];
        float A[4] = { cosf(thH), -sinf(thH), sinf(thH), cosf(thH) };
        float B[4] = { cosf(thL), -sinf(thL), sinf(thL), cosf(thL) };
        float G[16];
        for (int mp = 0; mp < 4; mp++)
            for (int m = 0; m < 4; m++) {
                float v = A[(mp >> 1) * 2 + (m >> 1)] * B[(mp & 1) * 2 + (m & 1)];
                G[mp * 4 + m] = (m == 3) ? -v : v;   // CZ applied first
            }
        if (stage == 0) {
            float bH = 0.5f * bias[i], bL = 0.5f * bias[i + 1];
            float Ab[4] = { cosf(bH), -sinf(bH), sinf(bH), cosf(bH) };
            float Bb[4] = { cosf(bL), -sinf(bL), sinf(bL), cosf(bL) };
            float Gb[16];
            for (int mp = 0; mp < 4; mp++)
                for (int m = 0; m < 4; m++)
                    Gb[mp * 4 + m] = Ab[(mp >> 1) * 2 + (m >> 1)] * Bb[(mp & 1) * 2 + (m & 1)];
            float GG[16];
            for (int a = 0; a < 4; a++)
                for (int c = 0; c < 4; c++) {
                    float s = 0.f;
                    for (int k = 0; k < 4; k++) s += G[a * 4 + k] * Gb[k * 4 + c];
                    GG[a * 4 + c] = s;               // apply bias first
                }
            for (int x = 0; x < 16; x++) G[x] = GG[x];
        }
        int gi = stage * 7 + p;
        for (int x = 0; x < 16; x++) sGp[gi * 16 + x] = pk2(G[x], G[x]);
        if (gi == 0 || gi == 14) {
            ull* c = sCv + (gi == 14 ? 8 : 0);
            c[0] = pk2(G[0],  G[5]);  c[1] = pk2(G[1],  G[4]);
            c[2] = pk2(G[2],  G[7]);  c[3] = pk2(G[3],  G[6]);
            c[4] = pk2(G[8],  G[13]); c[5] = pk2(G[9],  G[12]);
            c[6] = pk2(G[10], G[15]); c[7] = pk2(G[11], G[14]);
        }
    }

    // ---- P1: global load in tile order + sum-of-squares
    const ulonglong2* g4 = (const ulonglong2*)(in + (size_t)b * DIM);
    ulonglong2 v[16];
    ull ssp = 0ull;
    #pragma unroll
    for (int q = 0; q < 16; q++) {
        v[q] = g4[(t << 4) | q];
        ssp = f2fma(v[q].x, v[q].x, ssp);
        ssp = f2fma(v[q].y, v[q].y, ssp);
    }
    float s0, s1; up2(ssp, s0, s1);
    float ss = s0 + s1;
    #pragma unroll
    for (int o = 16; o; o >>= 1) ss += __shfl_xor_sync(0xffffffffu, ss, o);
    if ((t & 31) == 0) red[t >> 5] = ss;
    __syncthreads();                      // B1: gate tables + red
    if (t == 0) {
        float tot = 0.f;
        #pragma unroll
        for (int k = 0; k < 8; k++) tot += red[k];
        pinv[0] = 1.0f / tot;             // read in P7, ordered by B2..B7
    }

    // P1 gates, tile {0,1,2,3,4,5}: e0,e1,e2,o0,o1,f0,f1,p0  (8 gates)
    { C8   c = ldCv(sCv, 0);  op_vec2P(c, v); }        // e0 (1,0) packed
    { G16P g = ldGp(sGp, 1);  op_qlowP(g, v); }        // e1 (3,2)
    { G16P g = ldGp(sGp, 2);  op_qhighP(g, v); }       // e2 (5,4)
    { G16P g = ldGp(sGp, 7);  op_g21P(g, v); }         // o0 (2,1)
    { G16P g = ldGp(sGp, 8);  op_g43P(g, v); }         // o1 (4,3)
    { C8   c = ldCv(sCv, 1);  op_vec2P(c, v); }        // f0 (1,0) packed
    { G16P g = ldGp(sGp, 15); op_qlowP(g, v); }        // f1 (3,2)
    { G16P g = ldGp(sGp, 21); op_g21P(g, v); }         // p0 (2,1)
    { int base = swzF(t << 4); stvS<0>(s4, base, v); }
    __syncthreads();                      // B2

    // ---- P2, window f4{4..7}: e3,e4,o3
    { int base = swzF((t & 15) | ((t >> 4) << 8));
      ldvS<4>(s4, base, v);
      { G16P g = ldGp(sGp, 3);  op_qlowP(g, v); }      // e3 (7,6)
      { G16P g = ldGp(sGp, 4);  op_qhighP(g, v); }     // e4 (9,8)
      { G16P g = ldGp(sGp, 10); op_g43P(g, v); }       // o3 (8,7)
      stvS<4>(s4, base, v); }
    __syncthreads();                      // B3

    // ---- P3, window f4{8..11}: e5,e6,o5,f6(rows 2,3); store b13=1 half only
    { int base = swzF(t);
      ldvS<8>(s4, base, v);
      { G16P g = ldGp(sGp, 5);  op_qlowP(g, v); }      // e5 (11,10)
      { G16P g = ldGp(sGp, 6);  op_qhighP(g, v); }     // e6 (13,12)
      { G16P g = ldGp(sGp, 12); op_g43P(g, v); }       // o5 (12,11)
      { G16P g = ldGp(sGp, 20); op_qhighP_hi(g, v); }  // f6 (13,12), rows m=2,3
      stv8hi(s4, base, v); }
    __syncthreads();                      // B4

    // ---- P4, window f4{2..5} (amp 4..7): o2,f2,f3,p2 — b13=1 only
    if (t >= 128) {
      int base = swzF((t & 3) | ((t >> 2) << 6));      // f4 bit11 = t bit7 = 1
      ldvS<2>(s4, base, v);
      { G16P g = ldGp(sGp, 9);  op_g43P(g, v); }       // o2 (6,5)
      { G16P g = ldGp(sGp, 16); op_qlowP(g, v); }      // f2 (5,4)
      { G16P g = ldGp(sGp, 17); op_qhighP(g, v); }     // f3 (7,6)
      { G16P g = ldGp(sGp, 23); op_g43P(g, v); }       // p2 (6,5)
      stvS<2>(s4, base, v);
    }
    __syncthreads();                      // B5

    // ---- P5, window f4{6..9} (amp 8..11): o4,f4,f5,p4(rows 2,3) — b13=1
    //      store only q&4 half (amp b10=1); b10=0 outputs dead downstream
    if (t >= 128) {
      int base = swzF((t & 63) | ((t >> 6) << 10));    // f4 bit11 = t bit7 = 1
      ldvS<6>(s4, base, v);
      { G16P g = ldGp(sGp, 11); op_g43P(g, v); }       // o4 (10,9)
      { G16P g = ldGp(sGp, 18); op_qlowP(g, v); }      // f4 (9,8)
      { G16P g = ldGp(sGp, 19); op_qhighP(g, v); }     // f5 (11,10)
      { G16P g = ldGp(sGp, 25); op_g43P_hi(g, v); }    // p4 (10,9), rows m=2,3
      #pragma unroll
      for (int q = 0; q < 16; q++)
          if (q & 4) s4[base ^ swzF(q << 6)] = v[q];
    }
    __syncthreads();                      // B6

    // ---- P6', quarter cone {f4 b11=1, b8=1}: p1 (4,3) + p3 (8,7)
    if (t < 64) {
        int base = swzF((t & 1) | (((t >> 1) & 3) << 3) | (((t >> 3) & 1) << 7)
                        | (((t >> 4) & 3) << 9) | (1 << 8) | (1 << 11));
        #pragma unroll
        for (int q = 0; q < 16; q++) v[q] = s4[base ^ swzF(off6(q))];
        { G16P g = ldGp(sGp, 22); op_qlowP(g, v); }    // p1 (4,3) = q bits (1,0)
        { G16P g = ldGp(sGp, 24); op_qhighP(g, v); }   // p3 (8,7) = q bits (3,2)
        #pragma unroll
        for (int q = 0; q < 16; q++) s4[base ^ swzF(off6(q))] = v[q];
    }
    __syncthreads();                      // B7

    // ---- P7: p5 (12,11) row m=3 only + output (amps j >= 15384)
    if (t >= 6) {
        ulonglong2 v0 = s4[swzF(2304 + t)];   // amp (b12,b11)=(0,0)
        ulonglong2 v1 = s4[swzF(2816 + t)];   // (0,1)
        ulonglong2 v2 = s4[swzF(3328 + t)];   // (1,0)
        ulonglong2 v3 = s4[swzF(3840 + t)];   // (1,1)
        G16P g = ldGp(sGp, 26);                        // p5
        ull dx = f2fma(g.g[15], v3.x, f2fma(g.g[14], v2.x,
                 f2fma(g.g[13], v1.x, f2mul(g.g[12], v0.x))));
        ull dy = f2fma(g.g[15], v3.y, f2fma(g.g[14], v2.y,
                 f2fma(g.g[13], v1.y, f2mul(g.g[12], v0.y))));
        float inv = pinv[0];
        ull invp = pk2(inv, inv);
        ulonglong2 r;
        r.x = f2mul(f2mul(dx, dx), invp);
        r.y = f2mul(f2mul(dy, dy), invp);
        *(ulonglong2*)(out + (size_t)b * OUTN + 4 * t - 24) = r;
    }
}

extern "C" void kernel_launch(void* const* d_in, const int* in_sizes, int n_in,
                              void* d_out, int out_size) {
    const float* in   = (const float*)d_in[0];
    const float* w    = (const float*)d_in[1];
    const float* bias = (const float*)d_in[2];
    float* out = (float*)d_out;
    int B = in_sizes[0] / DIM;   // 512

    const int smem_bytes = (DIM + 896 + 32 + 8 + 8) * (int)sizeof(float);  // ~68 KB
    cudaFuncSetAttribute(qnn_main, cudaFuncAttributeMaxDynamicSharedMemorySize, smem_bytes);

    qnn_main<<<B, TPB, smem_bytes>>>(in, w, bias, out);
}